// round 2
// baseline (speedup 1.0000x reference)
#include <cuda_runtime.h>
#include <cuda_bf16.h>

#define N_NODES 100000
#define N_EDGES 1600000
#define HID 128
#define NGRAPH 64
#define NCLASS 10
#define NTILES ((N_NODES + 63) / 64)
#define SCAN_NB ((N_NODES + 1023) / 1024)

// ---------------- scratch (no allocations allowed) ----------------
__device__ float g_agg[N_NODES * HID];
__device__ float g_hA[N_NODES * HID];
__device__ float g_hB[N_NODES * HID];
__device__ int   g_cnt[N_NODES];        // histogram, then scatter cursor
__device__ int   g_off[N_NODES + 1];    // CSR offsets (by dst)
__device__ int   g_ssrc[N_EDGES];       // src ids sorted by dst
__device__ int   g_bsum[1024];          // scan partials
__device__ float g_pool[NGRAPH * HID];

typedef unsigned long long ull;

// ---------------- packed f32x2 helpers (Blackwell FFMA2) ----------------
__device__ __forceinline__ ull pack2(float a) {
    unsigned u = __float_as_uint(a);
    ull r;
    asm("mov.b64 %0, {%1, %1};" : "=l"(r) : "r"(u));
    return r;
}
__device__ __forceinline__ void fma2(ull& d, ull a, ull b) {
    asm("fma.rn.f32x2 %0, %1, %2, %0;" : "+l"(d) : "l"(a), "l"(b));
}
__device__ __forceinline__ void unpack2(ull v, float& lo, float& hi) {
    unsigned a, b;
    asm("mov.b64 {%0, %1}, %2;" : "=r"(a), "=r"(b) : "l"(v));
    lo = __uint_as_float(a);
    hi = __uint_as_float(b);
}

// ---------------- CSR build ----------------
__global__ void k_zero_i(int* p, int n) {
    int i = blockIdx.x * blockDim.x + threadIdx.x;
    if (i < n) p[i] = 0;
}
__global__ void k_zero_f(float* p, int n) {
    int i = blockIdx.x * blockDim.x + threadIdx.x;
    if (i < n) p[i] = 0.0f;
}
__global__ void k_hist(const int* __restrict__ dst) {
    int e = blockIdx.x * blockDim.x + threadIdx.x;
    if (e < N_EDGES) atomicAdd(&g_cnt[dst[e]], 1);
}
// blockwise exclusive scan of g_cnt -> g_off, block totals -> g_bsum
__global__ void k_scan1() {
    __shared__ int sh[1024];
    int t = threadIdx.x;
    int i = blockIdx.x * 1024 + t;
    int v = (i < N_NODES) ? g_cnt[i] : 0;
    sh[t] = v;
    __syncthreads();
    for (int d = 1; d < 1024; d <<= 1) {
        int tv = (t >= d) ? sh[t - d] : 0;
        __syncthreads();
        sh[t] += tv;
        __syncthreads();
    }
    if (i < N_NODES) g_off[i] = sh[t] - v;  // exclusive
    if (t == 1023) g_bsum[blockIdx.x] = sh[1023];
}
__global__ void k_scan2() {  // single block: exclusive scan of block sums
    __shared__ int sh[1024];
    int t = threadIdx.x;
    int v = (t < SCAN_NB) ? g_bsum[t] : 0;
    sh[t] = v;
    __syncthreads();
    for (int d = 1; d < 1024; d <<= 1) {
        int tv = (t >= d) ? sh[t - d] : 0;
        __syncthreads();
        sh[t] += tv;
        __syncthreads();
    }
    if (t < SCAN_NB) g_bsum[t] = sh[t] - v;  // exclusive
}
__global__ void k_scan3() {  // add block offsets, init cursor
    int i = blockIdx.x * blockDim.x + threadIdx.x;
    if (i < N_NODES) {
        int o = g_off[i] + g_bsum[i >> 10];
        g_off[i] = o;
        g_cnt[i] = o;  // cursor
    }
    if (i == 0) g_off[N_NODES] = N_EDGES;
}
__global__ void k_scatter(const int* __restrict__ src, const int* __restrict__ dst) {
    int e = blockIdx.x * blockDim.x + threadIdx.x;
    if (e < N_EDGES) {
        int d = dst[e];
        int pos = atomicAdd(&g_cnt[d], 1);
        g_ssrc[pos] = src[e];
    }
}

// ---------------- aggregation: one warp per node, 128 f32 = 32 lanes x float4 ----------------
__global__ void k_agg(const float4* __restrict__ hin, float4* __restrict__ agg) {
    int warp = (blockIdx.x * blockDim.x + threadIdx.x) >> 5;
    int lane = threadIdx.x & 31;
    if (warp >= N_NODES) return;
    int s = g_off[warp];
    int e = g_off[warp + 1];
    float4 acc = make_float4(0.f, 0.f, 0.f, 0.f);
    int j = s;
    for (; j + 1 < e; j += 2) {
        int s0 = __ldg(&g_ssrc[j]);
        int s1 = __ldg(&g_ssrc[j + 1]);
        float4 v0 = hin[s0 * 32 + lane];
        float4 v1 = hin[s1 * 32 + lane];
        acc.x += v0.x; acc.y += v0.y; acc.z += v0.z; acc.w += v0.w;
        acc.x += v1.x; acc.y += v1.y; acc.z += v1.z; acc.w += v1.w;
    }
    if (j < e) {
        int s0 = __ldg(&g_ssrc[j]);
        float4 v0 = hin[s0 * 32 + lane];
        acc.x += v0.x; acc.y += v0.y; acc.z += v0.z; acc.w += v0.w;
    }
    agg[warp * 32 + lane] = acc;
}

// ---------------- fused SAGE GEMM: out = relu?( [agg|hin] @ Ws + b ) ----------------
// Ws[k][o] in smem (stride 132), As[64][256] (stride 260). 256 threads:
// cg = tid&15 -> 8 output cols, rg = tid>>4 -> 4 node rows. FFMA2 inner loop.
#define WS_STRIDE 132
#define AS_STRIDE 260
#define SM_BYTES ((256 * WS_STRIDE + 64 * AS_STRIDE) * 4)

__global__ void __launch_bounds__(256, 1) k_sage(
    const float* __restrict__ agg, const float* __restrict__ hin,
    const float* __restrict__ Wl, const float* __restrict__ Wr,
    const float* __restrict__ bias, float* __restrict__ out, int do_relu) {
    extern __shared__ float sm[];
    float* Ws = sm;
    float* As = sm + 256 * WS_STRIDE;
    int tid = threadIdx.x;

    // load W transposed: coalesced gmem read, 4-way-conflict smem write (once per block)
    for (int idx = tid; idx < 16384; idx += 256) {
        int i = idx & 127;      // input dim
        int o = idx >> 7;       // output dim
        Ws[i * WS_STRIDE + o] = Wl[idx];              // Wl[o][i]
        Ws[(128 + i) * WS_STRIDE + o] = Wr[idx];      // Wr[o][i]
    }

    int cg = tid & 15;
    int rg = tid >> 4;
    float bb[8];
#pragma unroll
    for (int c = 0; c < 8; c++) bb[c] = bias[cg * 8 + c];
    __syncthreads();

    for (int tile = blockIdx.x; tile < NTILES; tile += gridDim.x) {
        int nbase = tile * 64;
        __syncthreads();  // previous tile's compute done before As overwrite
        // stage A = [agg | hin] for 64 nodes
        for (int idx = tid; idx < 4096; idx += 256) {
            int node = idx >> 6;
            int part = idx & 63;
            int gn = nbase + node;
            float4 v = make_float4(0.f, 0.f, 0.f, 0.f);
            if (gn < N_NODES) {
                v = (part < 32) ? ((const float4*)agg)[gn * 32 + part]
                                : ((const float4*)hin)[gn * 32 + (part - 32)];
            }
            *(float4*)&As[node * AS_STRIDE + part * 4] = v;
        }
        __syncthreads();

        ull acc[4][4];
#pragma unroll
        for (int j = 0; j < 4; j++)
#pragma unroll
            for (int p = 0; p < 4; p++) acc[j][p] = 0ull;

        int arow0 = (rg * 4) * AS_STRIDE;
        const float* wbase = &Ws[cg * 8];

#pragma unroll 2
        for (int k = 0; k < 256; k += 2) {
            ulonglong2 wa01 = *(const ulonglong2*)(wbase + k * WS_STRIDE);
            ulonglong2 wa23 = *(const ulonglong2*)(wbase + k * WS_STRIDE + 4);
            ulonglong2 wb01 = *(const ulonglong2*)(wbase + (k + 1) * WS_STRIDE);
            ulonglong2 wb23 = *(const ulonglong2*)(wbase + (k + 1) * WS_STRIDE + 4);
#pragma unroll
            for (int j = 0; j < 4; j++) {
                float2 a2 = *(const float2*)&As[arow0 + j * AS_STRIDE + k];
                ull aa = pack2(a2.x);
                ull ab = pack2(a2.y);
                fma2(acc[j][0], aa, wa01.x);
                fma2(acc[j][1], aa, wa01.y);
                fma2(acc[j][2], aa, wa23.x);
                fma2(acc[j][3], aa, wa23.y);
                fma2(acc[j][0], ab, wb01.x);
                fma2(acc[j][1], ab, wb01.y);
                fma2(acc[j][2], ab, wb23.x);
                fma2(acc[j][3], ab, wb23.y);
            }
        }

#pragma unroll
        for (int j = 0; j < 4; j++) {
            int gn = nbase + rg * 4 + j;
            if (gn < N_NODES) {
                float r[8];
#pragma unroll
                for (int p = 0; p < 4; p++) unpack2(acc[j][p], r[2 * p], r[2 * p + 1]);
#pragma unroll
                for (int c = 0; c < 8; c++) {
                    r[c] += bb[c];
                    if (do_relu && r[c] < 0.f) r[c] = 0.f;
                }
                float4 o0 = make_float4(r[0], r[1], r[2], r[3]);
                float4 o1 = make_float4(r[4], r[5], r[6], r[7]);
                ((float4*)out)[gn * 32 + cg * 2] = o0;
                ((float4*)out)[gn * 32 + cg * 2 + 1] = o1;
            }
        }
    }
}

// ---------------- pooling: batch is sorted -> run-length accumulate, few atomics ----------------
__global__ void k_pool(const float* __restrict__ h, const int* __restrict__ batch) {
    int base = blockIdx.x * 32;
    int col = threadIdx.x;  // 128 threads
    int end = base + 32;
    if (end > N_NODES) end = N_NODES;
    if (base >= N_NODES) return;
    int cur = batch[base];
    float sum = 0.f;
    for (int n = base; n < end; n++) {
        int b = batch[n];
        if (b != cur) {
            atomicAdd(&g_pool[cur * HID + col], sum);
            sum = 0.f;
            cur = b;
        }
        sum += h[n * HID + col];
    }
    atomicAdd(&g_pool[cur * HID + col], sum);
}

// ---------------- output head: [64,128] @ Wout^T + bout -> [64,10] ----------------
__global__ void k_out(const float* __restrict__ Wout, const float* __restrict__ bout,
                      float* __restrict__ out) {
    int t = threadIdx.x;
    if (t < NGRAPH * NCLASS) {
        int g = t / NCLASS;
        int c = t % NCLASS;
        float s = bout[c];
#pragma unroll 4
        for (int k = 0; k < HID; k++) s += g_pool[g * HID + k] * Wout[c * HID + k];
        out[t] = s;
    }
}

// ---------------- launch ----------------
extern "C" void kernel_launch(void* const* d_in, const int* in_sizes, int n_in,
                              void* d_out, int out_size) {
    const float* x = (const float*)d_in[0];
    const int* ei = (const int*)d_in[1];
    const int* src = ei;
    const int* dst = ei + N_EDGES;
    const int* batch = (const int*)d_in[2];
    const float* W1l = (const float*)d_in[3];
    const float* b1 = (const float*)d_in[4];
    const float* W1r = (const float*)d_in[5];
    const float* W2l = (const float*)d_in[6];
    const float* b2 = (const float*)d_in[7];
    const float* W2r = (const float*)d_in[8];
    const float* W3l = (const float*)d_in[9];
    const float* b3 = (const float*)d_in[10];
    const float* W3r = (const float*)d_in[11];
    const float* Wout = (const float*)d_in[12];
    const float* bout = (const float*)d_in[13];
    float* out = (float*)d_out;

    static int attr_done = 0;  // idempotent attribute set (same work every call)
    cudaFuncSetAttribute(k_sage, cudaFuncAttributeMaxDynamicSharedMemorySize, SM_BYTES);
    (void)attr_done;

    int* d_cnt;  cudaGetSymbolAddress((void**)&d_cnt, g_cnt);
    float* d_pool; cudaGetSymbolAddress((void**)&d_pool, g_pool);
    float* d_agg; cudaGetSymbolAddress((void**)&d_agg, g_agg);
    float* d_hA; cudaGetSymbolAddress((void**)&d_hA, g_hA);
    float* d_hB; cudaGetSymbolAddress((void**)&d_hB, g_hB);

    // CSR build
    k_zero_i<<<(N_NODES + 255) / 256, 256>>>(d_cnt, N_NODES);
    k_hist<<<(N_EDGES + 255) / 256, 256>>>(dst);
    k_scan1<<<SCAN_NB, 1024>>>();
    k_scan2<<<1, 1024>>>();
    k_scan3<<<(N_NODES + 255) / 256, 256>>>();
    k_scatter<<<(N_EDGES + 255) / 256, 256>>>(src, dst);

    // layer 1: x -> hA (relu)
    k_agg<<<(N_NODES + 7) / 8, 256>>>((const float4*)x, (float4*)d_agg);
    k_sage<<<148, 256, SM_BYTES>>>(d_agg, x, W1l, W1r, b1, d_hA, 1);
    // layer 2: hA -> hB (relu)
    k_agg<<<(N_NODES + 7) / 8, 256>>>((const float4*)d_hA, (float4*)d_agg);
    k_sage<<<148, 256, SM_BYTES>>>(d_agg, d_hA, W2l, W2r, b2, d_hB, 1);
    // layer 3: hB -> hA (no relu)
    k_agg<<<(N_NODES + 7) / 8, 256>>>((const float4*)d_hB, (float4*)d_agg);
    k_sage<<<148, 256, SM_BYTES>>>(d_agg, d_hB, W3l, W3r, b3, d_hA, 0);

    // pooling + head
    k_zero_f<<<(NGRAPH * HID + 255) / 256, 256>>>(d_pool, NGRAPH * HID);
    k_pool<<<(N_NODES + 31) / 32, 128>>>(d_hA, batch);
    k_out<<<1, 640>>>(Wout, bout, out);
}

// round 5
// speedup vs baseline: 1.7014x; 1.7014x over previous
#include <cuda_runtime.h>
#include <cuda_bf16.h>
#include <cstdint>

#define N_NODES 100000
#define N_EDGES 1600000
#define HID 128
#define NGRAPH 64
#define NCLASS 10
#define SCAN_NB ((N_NODES + 1023) / 1024)
#define NTILES128 ((N_NODES + 127) / 128)

// ---------------- scratch (no allocations allowed) ----------------
__device__ float g_agg[N_NODES * HID];
__device__ float g_hA[N_NODES * HID];
__device__ float g_hB[N_NODES * HID];
__device__ int   g_cnt[N_NODES];
__device__ int   g_off[N_NODES + 1];
__device__ int   g_ssrc[N_EDGES];
__device__ int   g_bsum[1024];
__device__ float g_pool[NGRAPH * HID];

// ---------------- CSR build ----------------
__global__ void k_zero_i(int* p, int n) {
    int i = blockIdx.x * blockDim.x + threadIdx.x;
    if (i < n) p[i] = 0;
}
__global__ void k_zero_f(float* p, int n) {
    int i = blockIdx.x * blockDim.x + threadIdx.x;
    if (i < n) p[i] = 0.0f;
}
__global__ void k_hist(const int* __restrict__ dst) {
    int e = blockIdx.x * blockDim.x + threadIdx.x;
    if (e < N_EDGES) atomicAdd(&g_cnt[dst[e]], 1);
}
__global__ void k_scan1() {
    __shared__ int sh[1024];
    int t = threadIdx.x;
    int i = blockIdx.x * 1024 + t;
    int v = (i < N_NODES) ? g_cnt[i] : 0;
    sh[t] = v;
    __syncthreads();
    for (int d = 1; d < 1024; d <<= 1) {
        int tv = (t >= d) ? sh[t - d] : 0;
        __syncthreads();
        sh[t] += tv;
        __syncthreads();
    }
    if (i < N_NODES) g_off[i] = sh[t] - v;
    if (t == 1023) g_bsum[blockIdx.x] = sh[1023];
}
__global__ void k_scan2() {
    __shared__ int sh[1024];
    int t = threadIdx.x;
    int v = (t < SCAN_NB) ? g_bsum[t] : 0;
    sh[t] = v;
    __syncthreads();
    for (int d = 1; d < 1024; d <<= 1) {
        int tv = (t >= d) ? sh[t - d] : 0;
        __syncthreads();
        sh[t] += tv;
        __syncthreads();
    }
    if (t < SCAN_NB) g_bsum[t] = sh[t] - v;
}
__global__ void k_scan3() {
    int i = blockIdx.x * blockDim.x + threadIdx.x;
    if (i < N_NODES) {
        int o = g_off[i] + g_bsum[i >> 10];
        g_off[i] = o;
        g_cnt[i] = o;
    }
    if (i == 0) g_off[N_NODES] = N_EDGES;
}
__global__ void k_scatter(const int* __restrict__ src, const int* __restrict__ dst) {
    int e = blockIdx.x * blockDim.x + threadIdx.x;
    if (e < N_EDGES) {
        int d = dst[e];
        int pos = atomicAdd(&g_cnt[d], 1);
        g_ssrc[pos] = src[e];
    }
}

// ---------------- aggregation: one warp per node ----------------
__global__ void k_agg(const float4* __restrict__ hin, float4* __restrict__ agg) {
    int warp = (blockIdx.x * blockDim.x + threadIdx.x) >> 5;
    int lane = threadIdx.x & 31;
    if (warp >= N_NODES) return;
    int s = g_off[warp];
    int e = g_off[warp + 1];
    float4 acc = make_float4(0.f, 0.f, 0.f, 0.f);
    int j = s;
    for (; j + 1 < e; j += 2) {
        int s0 = __ldg(&g_ssrc[j]);
        int s1 = __ldg(&g_ssrc[j + 1]);
        float4 v0 = hin[s0 * 32 + lane];
        float4 v1 = hin[s1 * 32 + lane];
        acc.x += v0.x; acc.y += v0.y; acc.z += v0.z; acc.w += v0.w;
        acc.x += v1.x; acc.y += v1.y; acc.z += v1.z; acc.w += v1.w;
    }
    if (j < e) {
        int s0 = __ldg(&g_ssrc[j]);
        float4 v0 = hin[s0 * 32 + lane];
        acc.x += v0.x; acc.y += v0.y; acc.z += v0.z; acc.w += v0.w;
    }
    agg[warp * 32 + lane] = acc;
}

// ---------------- mma.sync SAGE: out = relu?( [agg|hin] @ [Wl;Wr]^T + b ) ----------------
// Per CTA: 128 nodes x 128 outputs, K=256 in 2 chunks of 128 (A restaged).
// bf16 hi/lo split, 3 passes: Ah*Bh + Al*Bh + Ah*Bl, fp32 accumulators in regs.
// smem (bytes):
//   [0..512)     unused, [512..1024) bias
//   B hi: 128 rows x 528B (264 bf16, K=256 padded)   @ 1024
//   B lo: same                                        @ 1024+67584
//   A hi: 128 rows x 272B (136 bf16, K=128 padded)    @ ...
//   A lo: same
#define BROW 528
#define AROW 272
#define SB_H 1024
#define SB_L (SB_H + 128 * BROW)
#define SA_H (SB_L + 128 * BROW)
#define SA_L (SA_H + 128 * AROW)
#define SMEM_TC (SA_L + 128 * AROW)

__device__ __forceinline__ uint32_t pack_bf2(__nv_bfloat16 a, __nv_bfloat16 b) {
    return (uint32_t)__bfloat16_as_ushort(a) | ((uint32_t)__bfloat16_as_ushort(b) << 16);
}
__device__ __forceinline__ void split_store(char* sm, int hi_off, int lo_off,
                                            uint32_t byte_off, float x, float y) {
    __nv_bfloat16 h0 = __float2bfloat16(x), h1 = __float2bfloat16(y);
    float r0 = x - __bfloat162float(h0), r1 = y - __bfloat162float(h1);
    __nv_bfloat16 l0 = __float2bfloat16(r0), l1 = __float2bfloat16(r1);
    *(uint32_t*)(sm + hi_off + byte_off) = pack_bf2(h0, h1);
    *(uint32_t*)(sm + lo_off + byte_off) = pack_bf2(l0, l1);
}

__device__ __forceinline__ void mma16816(float* d, const uint32_t* a,
                                         uint32_t b0, uint32_t b1) {
    asm volatile(
        "mma.sync.aligned.m16n8k16.row.col.f32.bf16.bf16.f32 "
        "{%0,%1,%2,%3}, {%4,%5,%6,%7}, {%8,%9}, {%0,%1,%2,%3};"
        : "+f"(d[0]), "+f"(d[1]), "+f"(d[2]), "+f"(d[3])
        : "r"(a[0]), "r"(a[1]), "r"(a[2]), "r"(a[3]), "r"(b0), "r"(b1));
}

__global__ void __launch_bounds__(256, 1) k_sage_mma(
    const float* __restrict__ agg, const float* __restrict__ hin,
    const float* __restrict__ Wl, const float* __restrict__ Wr,
    const float* __restrict__ bias, float* __restrict__ out, int do_relu) {
    extern __shared__ char sm[];
    int tid = threadIdx.x;
    int wid = tid >> 5;
    int lane = tid & 31;
    int g = lane >> 2;       // group id 0..7
    int t4 = lane & 3;       // thread in group
    int wm = wid & 3;        // warp row block: rows wm*32..+31
    int wn = wid >> 2;       // warp col block: cols wn*64..+63
    int nbase = blockIdx.x * 128;
    float* sbias = (float*)(sm + 512);
    if (tid < HID) sbias[tid] = bias[tid];

    // ---- stage B = [Wl ; Wr] bf16 hi/lo, layout [o][k], row stride BROW ----
    for (int idx = tid; idx < 8192; idx += 256) {
        int o = idx >> 6, ip = idx & 63;                 // k = ip*2 (Wl half)
        float2 v = ((const float2*)Wl)[o * 64 + ip];
        split_store(sm, SB_H, SB_L, (uint32_t)(o * BROW + ip * 4), v.x, v.y);
    }
    for (int idx = tid; idx < 8192; idx += 256) {
        int o = idx >> 6, ip = idx & 63;                 // k = 128 + ip*2 (Wr half)
        float2 v = ((const float2*)Wr)[o * 64 + ip];
        split_store(sm, SB_H, SB_L, (uint32_t)(o * BROW + 256 + ip * 4), v.x, v.y);
    }

    float acc[2][8][4];
#pragma unroll
    for (int mt = 0; mt < 2; mt++)
#pragma unroll
        for (int n8 = 0; n8 < 8; n8++)
#pragma unroll
            for (int q = 0; q < 4; q++) acc[mt][n8][q] = 0.f;

    for (int chunk = 0; chunk < 2; chunk++) {
        const float* Asrc = chunk ? hin : agg;
        __syncthreads();  // previous chunk's mma reads done before A overwrite
        // ---- stage A chunk: 128 rows x 128 k, layout [row][k], stride AROW ----
        for (int idx = tid; idx < 8192; idx += 256) {
            int row = idx >> 6, ip = idx & 63;
            int gn = nbase + row;
            float2 v = make_float2(0.f, 0.f);
            if (gn < N_NODES) v = ((const float2*)Asrc)[gn * 64 + ip];
            split_store(sm, SA_H, SA_L, (uint32_t)(row * AROW + ip * 4), v.x, v.y);
        }
        __syncthreads();

#pragma unroll
        for (int pass = 0; pass < 3; pass++) {
            const char* Ab = sm + ((pass == 1) ? SA_L : SA_H);
            const char* Bb = sm + ((pass == 2) ? SB_L : SB_H);
#pragma unroll
            for (int k16 = 0; k16 < 8; k16++) {
                int ka = k16 * 16;            // k within A chunk
                int kb = chunk * 128 + ka;    // k within B (full K)
                uint32_t a[2][4];
#pragma unroll
                for (int mt = 0; mt < 2; mt++) {
                    int r0 = wm * 32 + mt * 16 + g;
                    int r1 = r0 + 8;
                    a[mt][0] = *(const uint32_t*)(Ab + r0 * AROW + (ka + t4 * 2) * 2);
                    a[mt][1] = *(const uint32_t*)(Ab + r1 * AROW + (ka + t4 * 2) * 2);
                    a[mt][2] = *(const uint32_t*)(Ab + r0 * AROW + (ka + 8 + t4 * 2) * 2);
                    a[mt][3] = *(const uint32_t*)(Ab + r1 * AROW + (ka + 8 + t4 * 2) * 2);
                }
#pragma unroll
                for (int n8 = 0; n8 < 8; n8++) {
                    int n = wn * 64 + n8 * 8 + g;
                    uint32_t b0 = *(const uint32_t*)(Bb + n * BROW + (kb + t4 * 2) * 2);
                    uint32_t b1 = *(const uint32_t*)(Bb + n * BROW + (kb + 8 + t4 * 2) * 2);
                    mma16816(acc[0][n8], a[0], b0, b1);
                    mma16816(acc[1][n8], a[1], b0, b1);
                }
            }
        }
    }

    // ---- epilogue: +bias, relu, store ----
#pragma unroll
    for (int mt = 0; mt < 2; mt++) {
        int r0 = wm * 32 + mt * 16 + g;
        int gn0 = nbase + r0;
        int gn1 = gn0 + 8;
#pragma unroll
        for (int n8 = 0; n8 < 8; n8++) {
            int col = wn * 64 + n8 * 8 + t4 * 2;
            float b0v = sbias[col], b1v = sbias[col + 1];
            if (gn0 < N_NODES) {
                float2 f;
                f.x = acc[mt][n8][0] + b0v;
                f.y = acc[mt][n8][1] + b1v;
                if (do_relu) { f.x = fmaxf(f.x, 0.f); f.y = fmaxf(f.y, 0.f); }
                *(float2*)(out + (size_t)gn0 * 128 + col) = f;
            }
            if (gn1 < N_NODES) {
                float2 f;
                f.x = acc[mt][n8][2] + b0v;
                f.y = acc[mt][n8][3] + b1v;
                if (do_relu) { f.x = fmaxf(f.x, 0.f); f.y = fmaxf(f.y, 0.f); }
                *(float2*)(out + (size_t)gn1 * 128 + col) = f;
            }
        }
    }
}

// ---------------- pooling ----------------
__global__ void k_pool(const float* __restrict__ h, const int* __restrict__ batch) {
    int base = blockIdx.x * 32;
    int col = threadIdx.x;
    int end = base + 32;
    if (end > N_NODES) end = N_NODES;
    if (base >= N_NODES) return;
    int cur = batch[base];
    float sum = 0.f;
    for (int n = base; n < end; n++) {
        int b = batch[n];
        if (b != cur) {
            atomicAdd(&g_pool[cur * HID + col], sum);
            sum = 0.f;
            cur = b;
        }
        sum += h[n * HID + col];
    }
    atomicAdd(&g_pool[cur * HID + col], sum);
}

// ---------------- output head ----------------
__global__ void k_out(const float* __restrict__ Wout, const float* __restrict__ bout,
                      float* __restrict__ out) {
    int t = threadIdx.x;
    if (t < NGRAPH * NCLASS) {
        int g = t / NCLASS;
        int c = t % NCLASS;
        float s = bout[c];
#pragma unroll 4
        for (int k = 0; k < HID; k++) s += g_pool[g * HID + k] * Wout[c * HID + k];
        out[t] = s;
    }
}

// ---------------- launch ----------------
extern "C" void kernel_launch(void* const* d_in, const int* in_sizes, int n_in,
                              void* d_out, int out_size) {
    const float* x = (const float*)d_in[0];
    const int* ei = (const int*)d_in[1];
    const int* src = ei;
    const int* dst = ei + N_EDGES;
    const int* batch = (const int*)d_in[2];
    const float* W1l = (const float*)d_in[3];
    const float* b1 = (const float*)d_in[4];
    const float* W1r = (const float*)d_in[5];
    const float* W2l = (const float*)d_in[6];
    const float* b2 = (const float*)d_in[7];
    const float* W2r = (const float*)d_in[8];
    const float* W3l = (const float*)d_in[9];
    const float* b3 = (const float*)d_in[10];
    const float* W3r = (const float*)d_in[11];
    const float* Wout = (const float*)d_in[12];
    const float* bout = (const float*)d_in[13];
    float* out = (float*)d_out;

    cudaFuncSetAttribute(k_sage_mma, cudaFuncAttributeMaxDynamicSharedMemorySize, SMEM_TC);

    int* d_cnt;  cudaGetSymbolAddress((void**)&d_cnt, g_cnt);
    float* d_pool; cudaGetSymbolAddress((void**)&d_pool, g_pool);
    float* d_agg; cudaGetSymbolAddress((void**)&d_agg, g_agg);
    float* d_hA; cudaGetSymbolAddress((void**)&d_hA, g_hA);
    float* d_hB; cudaGetSymbolAddress((void**)&d_hB, g_hB);

    // CSR build
    k_zero_i<<<(N_NODES + 255) / 256, 256>>>(d_cnt, N_NODES);
    k_hist<<<(N_EDGES + 255) / 256, 256>>>(dst);
    k_scan1<<<SCAN_NB, 1024>>>();
    k_scan2<<<1, 1024>>>();
    k_scan3<<<(N_NODES + 255) / 256, 256>>>();
    k_scatter<<<(N_EDGES + 255) / 256, 256>>>(src, dst);

    // layer 1: x -> hA (relu)
    k_agg<<<(N_NODES + 7) / 8, 256>>>((const float4*)x, (float4*)d_agg);
    k_sage_mma<<<NTILES128, 256, SMEM_TC>>>(d_agg, x, W1l, W1r, b1, d_hA, 1);
    // layer 2: hA -> hB (relu)
    k_agg<<<(N_NODES + 7) / 8, 256>>>((const float4*)d_hA, (float4*)d_agg);
    k_sage_mma<<<NTILES128, 256, SMEM_TC>>>(d_agg, d_hA, W2l, W2r, b2, d_hB, 1);
    // layer 3: hB -> hA (no relu)
    k_agg<<<(N_NODES + 7) / 8, 256>>>((const float4*)d_hB, (float4*)d_agg);
    k_sage_mma<<<NTILES128, 256, SMEM_TC>>>(d_agg, d_hB, W3l, W3r, b3, d_hA, 0);

    // pooling + head
    k_zero_f<<<(NGRAPH * HID + 255) / 256, 256>>>(d_pool, NGRAPH * HID);
    k_pool<<<(N_NODES + 31) / 32, 128>>>(d_hA, batch);
    k_out<<<1, 640>>>(Wout, bout, out);
}

// round 6
// speedup vs baseline: 1.8445x; 1.0841x over previous
#include <cuda_runtime.h>
#include <cuda_bf16.h>
#include <cuda_fp16.h>
#include <cstdint>

#define N_NODES 100000
#define N_EDGES 1600000
#define HID 128
#define NGRAPH 64
#define NCLASS 10
#define SCAN_NB ((N_NODES + 1023) / 1024)
#define NTILES128 ((N_NODES + 127) / 128)

// ---------------- scratch (no allocations allowed) ----------------
__device__ __half2 g_Z[N_NODES * 64];     // projected features, fp16
__device__ float   g_Y[N_NODES * HID];    // h@Wr^T + b, fp32
__device__ float   g_hA[N_NODES * HID];
__device__ float   g_hB[N_NODES * HID];
__device__ int     g_cnt[N_NODES];
__device__ int     g_off[N_NODES + 1];
__device__ int     g_ssrc[N_EDGES];
__device__ int     g_bsum[1024];
__device__ float   g_pool[NGRAPH * HID];

// ---------------- CSR build ----------------
__global__ void k_init() {
    int i = blockIdx.x * blockDim.x + threadIdx.x;
    if (i < N_NODES) g_cnt[i] = 0;
    if (i < NGRAPH * HID) g_pool[i] = 0.0f;
}
__global__ void k_hist(const int* __restrict__ dst) {
    int e = blockIdx.x * blockDim.x + threadIdx.x;
    if (e < N_EDGES) atomicAdd(&g_cnt[dst[e]], 1);
}
__global__ void k_scan1() {
    __shared__ int sh[1024];
    int t = threadIdx.x;
    int i = blockIdx.x * 1024 + t;
    int v = (i < N_NODES) ? g_cnt[i] : 0;
    sh[t] = v;
    __syncthreads();
    for (int d = 1; d < 1024; d <<= 1) {
        int tv = (t >= d) ? sh[t - d] : 0;
        __syncthreads();
        sh[t] += tv;
        __syncthreads();
    }
    if (i < N_NODES) g_off[i] = sh[t] - v;
    if (t == 1023) g_bsum[blockIdx.x] = sh[1023];
}
__global__ void k_scan2() {
    __shared__ int sh[1024];
    int t = threadIdx.x;
    int v = (t < SCAN_NB) ? g_bsum[t] : 0;
    sh[t] = v;
    __syncthreads();
    for (int d = 1; d < 1024; d <<= 1) {
        int tv = (t >= d) ? sh[t - d] : 0;
        __syncthreads();
        sh[t] += tv;
        __syncthreads();
    }
    if (t < SCAN_NB) g_bsum[t] = sh[t] - v;
}
__global__ void k_scan3() {
    int i = blockIdx.x * blockDim.x + threadIdx.x;
    if (i < N_NODES) {
        int o = g_off[i] + g_bsum[i >> 10];
        g_off[i] = o;
        g_cnt[i] = o;
    }
    if (i == 0) g_off[N_NODES] = N_EDGES;
}
__global__ void k_scatter(const int* __restrict__ src, const int* __restrict__ dst) {
    int e = blockIdx.x * blockDim.x + threadIdx.x;
    if (e < N_EDGES) {
        int d = dst[e];
        int pos = atomicAdd(&g_cnt[d], 1);
        g_ssrc[pos] = src[e];
    }
}

// ---------------- projection: Z = h@Wl^T (fp16), Y = h@Wr^T + b (fp32) ----------------
// Per CTA 128 nodes. B = [Wl;Wr] as 256 output rows x 128 K. bf16 hi/lo split,
// 3 passes (Ah*Bh + Al*Bh + Ah*Bl). 8 warps: wm(0..3) = 32-row block,
// wn(0..1) = 128-col block (wn=0 -> Z, wn=1 -> Y). ldmatrix.x4 fragments.
#define AROW 272
#define BROW 272
#define SB_H 1024
#define SB_L (SB_H + 256 * BROW)
#define SA_H (SB_L + 256 * BROW)
#define SA_L (SA_H + 128 * AROW)
#define SMEM_P (SA_L + 128 * AROW)

__device__ __forceinline__ uint32_t smem_u32(const void* p) {
    uint32_t a;
    asm("{ .reg .u64 t; cvta.to.shared.u64 t, %1; cvt.u32.u64 %0, t; }"
        : "=r"(a) : "l"(p));
    return a;
}
__device__ __forceinline__ uint32_t pack_bf2(__nv_bfloat16 a, __nv_bfloat16 b) {
    return (uint32_t)__bfloat16_as_ushort(a) | ((uint32_t)__bfloat16_as_ushort(b) << 16);
}
__device__ __forceinline__ void split_store(char* sm, int hi_off, int lo_off,
                                            uint32_t byte_off, float x, float y) {
    __nv_bfloat16 h0 = __float2bfloat16(x), h1 = __float2bfloat16(y);
    float r0 = x - __bfloat162float(h0), r1 = y - __bfloat162float(h1);
    __nv_bfloat16 l0 = __float2bfloat16(r0), l1 = __float2bfloat16(r1);
    *(uint32_t*)(sm + hi_off + byte_off) = pack_bf2(h0, h1);
    *(uint32_t*)(sm + lo_off + byte_off) = pack_bf2(l0, l1);
}
__device__ __forceinline__ void mma16816(float* d, const uint32_t* a,
                                         uint32_t b0, uint32_t b1) {
    asm volatile(
        "mma.sync.aligned.m16n8k16.row.col.f32.bf16.bf16.f32 "
        "{%0,%1,%2,%3}, {%4,%5,%6,%7}, {%8,%9}, {%0,%1,%2,%3};"
        : "+f"(d[0]), "+f"(d[1]), "+f"(d[2]), "+f"(d[3])
        : "r"(a[0]), "r"(a[1]), "r"(a[2]), "r"(a[3]), "r"(b0), "r"(b1));
}
#define LDSM_X4(r0, r1, r2, r3, addr)                                        \
    asm volatile("ldmatrix.sync.aligned.m8n8.x4.shared.b16 {%0,%1,%2,%3}, [%4];" \
                 : "=r"(r0), "=r"(r1), "=r"(r2), "=r"(r3) : "r"(addr))

__global__ void __launch_bounds__(256, 1) k_proj(
    const float* __restrict__ h, const float* __restrict__ Wl,
    const float* __restrict__ Wr, const float* __restrict__ bias,
    __half2* __restrict__ Z, float* __restrict__ Y) {
    extern __shared__ char sm[];
    int tid = threadIdx.x;
    int wid = tid >> 5;
    int lane = tid & 31;
    int g = lane >> 2;
    int t4 = lane & 3;
    int wm = wid & 3;     // 32-row block
    int wn = wid >> 2;    // 0 -> Z cols, 1 -> Y cols
    int nbase = blockIdx.x * 128;
    float* sbias = (float*)(sm + 512);
    if (tid < HID) sbias[tid] = bias[tid];

    // stage B: Wl rows 0..127, Wr rows 128..255  (row = output o, cols = K)
    for (int idx = tid; idx < 8192; idx += 256) {
        int o = idx >> 6, ip = idx & 63;
        float2 v = ((const float2*)Wl)[o * 64 + ip];
        split_store(sm, SB_H, SB_L, (uint32_t)(o * BROW + ip * 4), v.x, v.y);
    }
    for (int idx = tid; idx < 8192; idx += 256) {
        int o = idx >> 6, ip = idx & 63;
        float2 v = ((const float2*)Wr)[o * 64 + ip];
        split_store(sm, SB_H, SB_L, (uint32_t)((o + 128) * BROW + ip * 4), v.x, v.y);
    }
    // stage A: 128 node rows x 128 K
    for (int idx = tid; idx < 8192; idx += 256) {
        int row = idx >> 6, ip = idx & 63;
        int gn = nbase + row;
        float2 v = make_float2(0.f, 0.f);
        if (gn < N_NODES) v = ((const float2*)h)[gn * 64 + ip];
        split_store(sm, SA_H, SA_L, (uint32_t)(row * AROW + ip * 4), v.x, v.y);
    }
    __syncthreads();

    uint32_t smb = smem_u32(sm);
    // ldmatrix lane offsets (bytes within plane)
    uint32_t a_off0 = (uint32_t)((wm * 32 + (lane & 15)) * AROW + ((lane >> 4) * 8) * 2);
    uint32_t a_off1 = a_off0 + 16 * AROW;
    uint32_t b_off = (uint32_t)((wn * 128 + (lane & 7) + ((lane & 16) ? 8 : 0)) * BROW +
                                ((lane & 8) ? 16 : 0));

    float acc[2][16][4];
#pragma unroll
    for (int mt = 0; mt < 2; mt++)
#pragma unroll
        for (int n8 = 0; n8 < 16; n8++)
#pragma unroll
            for (int q = 0; q < 4; q++) acc[mt][n8][q] = 0.f;

#pragma unroll
    for (int pass = 0; pass < 3; pass++) {
        uint32_t Ab = smb + ((pass == 1) ? SA_L : SA_H);
        uint32_t Bb = smb + ((pass == 2) ? SB_L : SB_H);
#pragma unroll
        for (int k16 = 0; k16 < 8; k16++) {
            uint32_t ka = (uint32_t)(k16 * 32);  // 16 elems * 2B
            uint32_t a[2][4];
            LDSM_X4(a[0][0], a[0][1], a[0][2], a[0][3], Ab + a_off0 + ka);
            LDSM_X4(a[1][0], a[1][1], a[1][2], a[1][3], Ab + a_off1 + ka);
#pragma unroll
            for (int p = 0; p < 8; p++) {
                uint32_t b0, b1, b2, b3;
                LDSM_X4(b0, b1, b2, b3, Bb + b_off + (uint32_t)(p * 16 * BROW) + ka);
                mma16816(acc[0][2 * p], a[0], b0, b1);
                mma16816(acc[0][2 * p + 1], a[0], b2, b3);
                mma16816(acc[1][2 * p], a[1], b0, b1);
                mma16816(acc[1][2 * p + 1], a[1], b2, b3);
            }
        }
    }

    // epilogue
#pragma unroll
    for (int mt = 0; mt < 2; mt++) {
        int r0 = wm * 32 + mt * 16 + g;
        int gn0 = nbase + r0;
        int gn1 = gn0 + 8;
#pragma unroll
        for (int n8 = 0; n8 < 16; n8++) {
            int col = n8 * 8 + t4 * 2;  // within this warp's 128-col block
            if (wn == 0) {
                // Z fp16
                if (gn0 < N_NODES)
                    Z[gn0 * 64 + (col >> 1)] = __floats2half2_rn(acc[mt][n8][0], acc[mt][n8][1]);
                if (gn1 < N_NODES)
                    Z[gn1 * 64 + (col >> 1)] = __floats2half2_rn(acc[mt][n8][2], acc[mt][n8][3]);
            } else {
                float b0v = sbias[col], b1v = sbias[col + 1];
                if (gn0 < N_NODES) {
                    float2 f = make_float2(acc[mt][n8][0] + b0v, acc[mt][n8][1] + b1v);
                    *(float2*)(Y + (size_t)gn0 * 128 + col) = f;
                }
                if (gn1 < N_NODES) {
                    float2 f = make_float2(acc[mt][n8][2] + b0v, acc[mt][n8][3] + b1v);
                    *(float2*)(Y + (size_t)gn1 * 128 + col) = f;
                }
            }
        }
    }
}

// ---------------- aggregation on fp16 Z: out = relu?( S@Z + Y ) ----------------
__global__ void k_agg2(const uint2* __restrict__ Z, const float4* __restrict__ Y,
                       float4* __restrict__ out, int do_relu) {
    int warp = (blockIdx.x * blockDim.x + threadIdx.x) >> 5;
    int lane = threadIdx.x & 31;
    if (warp >= N_NODES) return;
    int s = g_off[warp];
    int e = g_off[warp + 1];
    float4 acc = make_float4(0.f, 0.f, 0.f, 0.f);
    int j = s;
    for (; j + 1 < e; j += 2) {
        int s0 = __ldg(&g_ssrc[j]);
        int s1 = __ldg(&g_ssrc[j + 1]);
        uint2 v0 = Z[s0 * 32 + lane];
        uint2 v1 = Z[s1 * 32 + lane];
        float2 f0 = __half22float2(*(const __half2*)&v0.x);
        float2 f1 = __half22float2(*(const __half2*)&v0.y);
        float2 f2 = __half22float2(*(const __half2*)&v1.x);
        float2 f3 = __half22float2(*(const __half2*)&v1.y);
        acc.x += f0.x + f2.x;
        acc.y += f0.y + f2.y;
        acc.z += f1.x + f3.x;
        acc.w += f1.y + f3.y;
    }
    if (j < e) {
        int s0 = __ldg(&g_ssrc[j]);
        uint2 v0 = Z[s0 * 32 + lane];
        float2 f0 = __half22float2(*(const __half2*)&v0.x);
        float2 f1 = __half22float2(*(const __half2*)&v0.y);
        acc.x += f0.x;
        acc.y += f0.y;
        acc.z += f1.x;
        acc.w += f1.y;
    }
    float4 y = Y[warp * 32 + lane];
    float4 r;
    r.x = acc.x + y.x;
    r.y = acc.y + y.y;
    r.z = acc.z + y.z;
    r.w = acc.w + y.w;
    if (do_relu) {
        r.x = fmaxf(r.x, 0.f);
        r.y = fmaxf(r.y, 0.f);
        r.z = fmaxf(r.z, 0.f);
        r.w = fmaxf(r.w, 0.f);
    }
    out[warp * 32 + lane] = r;
}

// ---------------- pooling ----------------
__global__ void k_pool(const float* __restrict__ h, const int* __restrict__ batch) {
    int base = blockIdx.x * 32;
    int col = threadIdx.x;
    int end = base + 32;
    if (end > N_NODES) end = N_NODES;
    if (base >= N_NODES) return;
    int cur = batch[base];
    float sum = 0.f;
    for (int n = base; n < end; n++) {
        int b = batch[n];
        if (b != cur) {
            atomicAdd(&g_pool[cur * HID + col], sum);
            sum = 0.f;
            cur = b;
        }
        sum += h[n * HID + col];
    }
    atomicAdd(&g_pool[cur * HID + col], sum);
}

// ---------------- output head ----------------
__global__ void k_out(const float* __restrict__ Wout, const float* __restrict__ bout,
                      float* __restrict__ out) {
    int t = threadIdx.x;
    if (t < NGRAPH * NCLASS) {
        int g = t / NCLASS;
        int c = t % NCLASS;
        float s = bout[c];
#pragma unroll 4
        for (int k = 0; k < HID; k++) s += g_pool[g * HID + k] * Wout[c * HID + k];
        out[t] = s;
    }
}

// ---------------- launch ----------------
extern "C" void kernel_launch(void* const* d_in, const int* in_sizes, int n_in,
                              void* d_out, int out_size) {
    const float* x = (const float*)d_in[0];
    const int* ei = (const int*)d_in[1];
    const int* src = ei;
    const int* dst = ei + N_EDGES;
    const int* batch = (const int*)d_in[2];
    const float* W1l = (const float*)d_in[3];
    const float* b1 = (const float*)d_in[4];
    const float* W1r = (const float*)d_in[5];
    const float* W2l = (const float*)d_in[6];
    const float* b2 = (const float*)d_in[7];
    const float* W2r = (const float*)d_in[8];
    const float* W3l = (const float*)d_in[9];
    const float* b3 = (const float*)d_in[10];
    const float* W3r = (const float*)d_in[11];
    const float* Wout = (const float*)d_in[12];
    const float* bout = (const float*)d_in[13];
    float* out = (float*)d_out;

    cudaFuncSetAttribute(k_proj, cudaFuncAttributeMaxDynamicSharedMemorySize, SMEM_P);

    __half2* d_Z; cudaGetSymbolAddress((void**)&d_Z, g_Z);
    float* d_Y;  cudaGetSymbolAddress((void**)&d_Y, g_Y);
    float* d_hA; cudaGetSymbolAddress((void**)&d_hA, g_hA);
    float* d_hB; cudaGetSymbolAddress((void**)&d_hB, g_hB);

    // CSR build
    k_init<<<(N_NODES + 255) / 256, 256>>>();
    k_hist<<<(N_EDGES + 255) / 256, 256>>>(dst);
    k_scan1<<<SCAN_NB, 1024>>>();
    k_scan2<<<1, 1024>>>();
    k_scan3<<<(N_NODES + 255) / 256, 256>>>();
    k_scatter<<<(N_EDGES + 255) / 256, 256>>>(src, dst);

    // layer 1: x -> hA (relu)
    k_proj<<<NTILES128, 256, SMEM_P>>>(x, W1l, W1r, b1, d_Z, d_Y);
    k_agg2<<<(N_NODES + 7) / 8, 256>>>((const uint2*)d_Z, (const float4*)d_Y,
                                       (float4*)d_hA, 1);
    // layer 2: hA -> hB (relu)
    k_proj<<<NTILES128, 256, SMEM_P>>>(d_hA, W2l, W2r, b2, d_Z, d_Y);
    k_agg2<<<(N_NODES + 7) / 8, 256>>>((const uint2*)d_Z, (const float4*)d_Y,
                                       (float4*)d_hB, 1);
    // layer 3: hB -> hA (no relu)
    k_proj<<<NTILES128, 256, SMEM_P>>>(d_hB, W3l, W3r, b3, d_Z, d_Y);
    k_agg2<<<(N_NODES + 7) / 8, 256>>>((const uint2*)d_Z, (const float4*)d_Y,
                                       (float4*)d_hA, 0);

    // pooling + head
    k_pool<<<(N_NODES + 31) / 32, 128>>>(d_hA, batch);
    k_out<<<1, 640>>>(Wout, bout, out);
}

// round 7
// speedup vs baseline: 2.0720x; 1.1234x over previous
#include <cuda_runtime.h>
#include <cuda_bf16.h>
#include <cuda_fp16.h>
#include <cstdint>

#define N_NODES 100000
#define N_EDGES 1600000
#define HID 128
#define NGRAPH 64
#define NCLASS 10
#define SCAN_NB ((N_NODES + 1023) / 1024)
#define NTILES128 ((N_NODES + 127) / 128)
#define PROJ_GRID 148

// ---------------- scratch (no allocations allowed) ----------------
__device__ uint4  g_Z[N_NODES * 16];      // projected features (h@Wl^T), fp16, 256B/row
__device__ uint4  g_Y[N_NODES * 16];      // h@Wr^T + b, fp16, 256B/row
__device__ float4 g_hA[N_NODES * 32];
__device__ float4 g_hB[N_NODES * 32];
__device__ uint4  g_Bh[3 * 4096];         // per-layer [Wl;Wr] bf16 hi (64KB each)
__device__ uint4  g_Bl[3 * 4096];         // per-layer lo
__device__ int    g_cnt[N_NODES];
__device__ int    g_off[N_NODES + 1];
__device__ int    g_ssrc[N_EDGES];
__device__ int    g_bsum[1024];
__device__ float  g_pool[NGRAPH * HID];

// ---------------- CSR build ----------------
__global__ void k_init() {
    int i = blockIdx.x * blockDim.x + threadIdx.x;
    if (i < N_NODES) g_cnt[i] = 0;
    if (i < NGRAPH * HID) g_pool[i] = 0.0f;
}
__global__ void k_hist(const int* __restrict__ dst) {
    int e = blockIdx.x * blockDim.x + threadIdx.x;
    if (e < N_EDGES) atomicAdd(&g_cnt[dst[e]], 1);
}
__global__ void k_scan1() {
    __shared__ int sh[1024];
    int t = threadIdx.x;
    int i = blockIdx.x * 1024 + t;
    int v = (i < N_NODES) ? g_cnt[i] : 0;
    sh[t] = v;
    __syncthreads();
    for (int d = 1; d < 1024; d <<= 1) {
        int tv = (t >= d) ? sh[t - d] : 0;
        __syncthreads();
        sh[t] += tv;
        __syncthreads();
    }
    if (i < N_NODES) g_off[i] = sh[t] - v;
    if (t == 1023) g_bsum[blockIdx.x] = sh[1023];
}
__global__ void k_scan2() {
    __shared__ int sh[1024];
    int t = threadIdx.x;
    int v = (t < SCAN_NB) ? g_bsum[t] : 0;
    sh[t] = v;
    __syncthreads();
    for (int d = 1; d < 1024; d <<= 1) {
        int tv = (t >= d) ? sh[t - d] : 0;
        __syncthreads();
        sh[t] += tv;
        __syncthreads();
    }
    if (t < SCAN_NB) g_bsum[t] = sh[t] - v;
}
__global__ void k_scan3() {
    int i = blockIdx.x * blockDim.x + threadIdx.x;
    if (i < N_NODES) {
        int o = g_off[i] + g_bsum[i >> 10];
        g_off[i] = o;
        g_cnt[i] = o;
    }
    if (i == 0) g_off[N_NODES] = N_EDGES;
}
__global__ void k_scatter(const int* __restrict__ src, const int* __restrict__ dst) {
    int e = blockIdx.x * blockDim.x + threadIdx.x;
    if (e < N_EDGES) {
        int d = dst[e];
        int pos = atomicAdd(&g_cnt[d], 1);
        g_ssrc[pos] = src[e];
    }
}

// ---------------- weight precompute: [Wl;Wr] -> bf16 hi/lo, row-major [256][128] ----
__global__ void k_wprep(const float* __restrict__ Wl, const float* __restrict__ Wr,
                        __nv_bfloat16* __restrict__ Bh, __nv_bfloat16* __restrict__ Bl) {
    int idx = blockIdx.x * blockDim.x + threadIdx.x;
    if (idx >= 32768) return;
    int o = idx >> 7, k = idx & 127;
    float f = (o < 128) ? Wl[o * 128 + k] : Wr[(o - 128) * 128 + k];
    __nv_bfloat16 h = __float2bfloat16(f);
    Bh[idx] = h;
    Bl[idx] = __float2bfloat16(f - __bfloat162float(h));
}

// ---------------- persistent projection: Z = h@Wl^T (fp16), Y = h@Wr^T + b (fp16) ----
// B resident per CTA (staged once from precomputed bf16 hi/lo). A staged per tile.
// 3 passes: Ah*Bh + Al*Bh + Ah*Bl, fp32 accum. ldmatrix.x4 fragments.
#define AROW 272
#define BROW 272
#define SB_H 1024
#define SB_L (SB_H + 256 * BROW)
#define SA_H (SB_L + 256 * BROW)
#define SA_L (SA_H + 128 * AROW)
#define SMEM_P (SA_L + 128 * AROW)

__device__ __forceinline__ uint32_t smem_u32(const void* p) {
    uint32_t a;
    asm("{ .reg .u64 t; cvta.to.shared.u64 t, %1; cvt.u32.u64 %0, t; }"
        : "=r"(a) : "l"(p));
    return a;
}
__device__ __forceinline__ uint32_t pack_bf2(__nv_bfloat16 a, __nv_bfloat16 b) {
    return (uint32_t)__bfloat16_as_ushort(a) | ((uint32_t)__bfloat16_as_ushort(b) << 16);
}
__device__ __forceinline__ void split_store(char* sm, int hi_off, int lo_off,
                                            uint32_t byte_off, float x, float y) {
    __nv_bfloat16 h0 = __float2bfloat16(x), h1 = __float2bfloat16(y);
    float r0 = x - __bfloat162float(h0), r1 = y - __bfloat162float(h1);
    __nv_bfloat16 l0 = __float2bfloat16(r0), l1 = __float2bfloat16(r1);
    *(uint32_t*)(sm + hi_off + byte_off) = pack_bf2(h0, h1);
    *(uint32_t*)(sm + lo_off + byte_off) = pack_bf2(l0, l1);
}
__device__ __forceinline__ void mma16816(float* d, const uint32_t* a,
                                         uint32_t b0, uint32_t b1) {
    asm volatile(
        "mma.sync.aligned.m16n8k16.row.col.f32.bf16.bf16.f32 "
        "{%0,%1,%2,%3}, {%4,%5,%6,%7}, {%8,%9}, {%0,%1,%2,%3};"
        : "+f"(d[0]), "+f"(d[1]), "+f"(d[2]), "+f"(d[3])
        : "r"(a[0]), "r"(a[1]), "r"(a[2]), "r"(a[3]), "r"(b0), "r"(b1));
}
#define LDSM_X4(r0, r1, r2, r3, addr)                                        \
    asm volatile("ldmatrix.sync.aligned.m8n8.x4.shared.b16 {%0,%1,%2,%3}, [%4];" \
                 : "=r"(r0), "=r"(r1), "=r"(r2), "=r"(r3) : "r"(addr))

__global__ void __launch_bounds__(256, 1) k_proj(
    const float* __restrict__ h, const uint4* __restrict__ BhG,
    const uint4* __restrict__ BlG, const float* __restrict__ bias,
    uint4* __restrict__ Z, uint4* __restrict__ Y) {
    extern __shared__ char sm[];
    int tid = threadIdx.x;
    int wid = tid >> 5;
    int lane = tid & 31;
    int g = lane >> 2;
    int t4 = lane & 3;
    int wm = wid & 3;     // 32-row block
    int wn = wid >> 2;    // 0 -> Z cols, 1 -> Y cols
    float* sbias = (float*)(sm + 512);
    if (tid < HID) sbias[tid] = bias[tid];

    // stage B once per CTA from precomputed bf16 (64KB hi + 64KB lo)
    for (int idx = tid; idx < 4096; idx += 256) {
        int o = idx >> 4, c = idx & 15;
        *(uint4*)(sm + SB_H + o * BROW + c * 16) = BhG[idx];
        *(uint4*)(sm + SB_L + o * BROW + c * 16) = BlG[idx];
    }

    uint32_t smb = smem_u32(sm);
    uint32_t a_off0 = (uint32_t)((wm * 32 + (lane & 15)) * AROW + ((lane >> 4) * 8) * 2);
    uint32_t a_off1 = a_off0 + 16 * AROW;
    uint32_t b_off = (uint32_t)((wn * 128 + (lane & 7) + ((lane & 16) ? 8 : 0)) * BROW +
                                ((lane & 8) ? 16 : 0));

    for (int tile = blockIdx.x; tile < NTILES128; tile += gridDim.x) {
        int nbase = tile * 128;
        __syncthreads();  // previous tile fully consumed (and B staged, first iter)
        for (int idx = tid; idx < 8192; idx += 256) {
            int row = idx >> 6, ip = idx & 63;
            int gn = nbase + row;
            float2 v = make_float2(0.f, 0.f);
            if (gn < N_NODES) v = ((const float2*)h)[gn * 64 + ip];
            split_store(sm, SA_H, SA_L, (uint32_t)(row * AROW + ip * 4), v.x, v.y);
        }
        __syncthreads();

        float acc[2][16][4];
#pragma unroll
        for (int mt = 0; mt < 2; mt++)
#pragma unroll
            for (int n8 = 0; n8 < 16; n8++)
#pragma unroll
                for (int q = 0; q < 4; q++) acc[mt][n8][q] = 0.f;

#pragma unroll
        for (int pass = 0; pass < 3; pass++) {
            uint32_t Ab = smb + ((pass == 1) ? SA_L : SA_H);
            uint32_t Bb = smb + ((pass == 2) ? SB_L : SB_H);
#pragma unroll
            for (int k16 = 0; k16 < 8; k16++) {
                uint32_t ka = (uint32_t)(k16 * 32);
                uint32_t a[2][4];
                LDSM_X4(a[0][0], a[0][1], a[0][2], a[0][3], Ab + a_off0 + ka);
                LDSM_X4(a[1][0], a[1][1], a[1][2], a[1][3], Ab + a_off1 + ka);
#pragma unroll
                for (int p = 0; p < 8; p++) {
                    uint32_t b0, b1, b2, b3;
                    LDSM_X4(b0, b1, b2, b3, Bb + b_off + (uint32_t)(p * 16 * BROW) + ka);
                    mma16816(acc[0][2 * p], a[0], b0, b1);
                    mma16816(acc[0][2 * p + 1], a[0], b2, b3);
                    mma16816(acc[1][2 * p], a[1], b0, b1);
                    mma16816(acc[1][2 * p + 1], a[1], b2, b3);
                }
            }
        }

        // epilogue: wn=0 -> Z (fp16), wn=1 -> Y = +bias (fp16)
        __half2* Zh = (__half2*)Z;
        __half2* Yh = (__half2*)Y;
#pragma unroll
        for (int mt = 0; mt < 2; mt++) {
            int r0 = wm * 32 + mt * 16 + g;
            int gn0 = nbase + r0;
            int gn1 = gn0 + 8;
#pragma unroll
            for (int n8 = 0; n8 < 16; n8++) {
                int col = n8 * 8 + t4 * 2;
                if (wn == 0) {
                    if (gn0 < N_NODES)
                        Zh[gn0 * 64 + (col >> 1)] =
                            __floats2half2_rn(acc[mt][n8][0], acc[mt][n8][1]);
                    if (gn1 < N_NODES)
                        Zh[gn1 * 64 + (col >> 1)] =
                            __floats2half2_rn(acc[mt][n8][2], acc[mt][n8][3]);
                } else {
                    float b0v = sbias[col], b1v = sbias[col + 1];
                    if (gn0 < N_NODES)
                        Yh[gn0 * 64 + (col >> 1)] =
                            __floats2half2_rn(acc[mt][n8][0] + b0v, acc[mt][n8][1] + b1v);
                    if (gn1 < N_NODES)
                        Yh[gn1 * 64 + (col >> 1)] =
                            __floats2half2_rn(acc[mt][n8][2] + b0v, acc[mt][n8][3] + b1v);
                }
            }
        }
    }
}

// ---------------- aggregation: out = relu?( S@Z + Y ), 2 nodes/warp, 16 lanes ea ----
__global__ void k_agg2(const uint4* __restrict__ Z, const uint4* __restrict__ Y,
                       float4* __restrict__ out, int do_relu) {
    int w = (blockIdx.x * blockDim.x + threadIdx.x) >> 5;
    int lane = threadIdx.x & 31;
    int node = w * 2 + (lane >> 4);
    int l16 = lane & 15;
    if (node >= N_NODES) return;
    int s = g_off[node];
    int e = g_off[node + 1];
    float acc[8];
#pragma unroll
    for (int q = 0; q < 8; q++) acc[q] = 0.f;

    int j = s;
    for (; j + 3 < e; j += 4) {
        int s0 = __ldg(&g_ssrc[j]);
        int s1 = __ldg(&g_ssrc[j + 1]);
        int s2 = __ldg(&g_ssrc[j + 2]);
        int s3 = __ldg(&g_ssrc[j + 3]);
        uint4 v0 = Z[s0 * 16 + l16];
        uint4 v1 = Z[s1 * 16 + l16];
        uint4 v2 = Z[s2 * 16 + l16];
        uint4 v3 = Z[s3 * 16 + l16];
#pragma unroll
        for (int q = 0; q < 4; q++) {
            uint32_t u0 = (&v0.x)[q], u1 = (&v1.x)[q], u2 = (&v2.x)[q], u3 = (&v3.x)[q];
            float2 f0 = __half22float2(*(__half2*)&u0);
            float2 f1 = __half22float2(*(__half2*)&u1);
            float2 f2 = __half22float2(*(__half2*)&u2);
            float2 f3 = __half22float2(*(__half2*)&u3);
            acc[2 * q] += (f0.x + f1.x) + (f2.x + f3.x);
            acc[2 * q + 1] += (f0.y + f1.y) + (f2.y + f3.y);
        }
    }
    for (; j < e; j++) {
        int s0 = __ldg(&g_ssrc[j]);
        uint4 v0 = Z[s0 * 16 + l16];
#pragma unroll
        for (int q = 0; q < 4; q++) {
            uint32_t u0 = (&v0.x)[q];
            float2 f0 = __half22float2(*(__half2*)&u0);
            acc[2 * q] += f0.x;
            acc[2 * q + 1] += f0.y;
        }
    }

    uint4 yv = Y[node * 16 + l16];
#pragma unroll
    for (int q = 0; q < 4; q++) {
        uint32_t u = (&yv.x)[q];
        float2 f = __half22float2(*(__half2*)&u);
        acc[2 * q] += f.x;
        acc[2 * q + 1] += f.y;
    }
    if (do_relu) {
#pragma unroll
        for (int q = 0; q < 8; q++) acc[q] = fmaxf(acc[q], 0.f);
    }
    out[node * 32 + l16 * 2] = make_float4(acc[0], acc[1], acc[2], acc[3]);
    out[node * 32 + l16 * 2 + 1] = make_float4(acc[4], acc[5], acc[6], acc[7]);
}

// ---------------- pooling ----------------
__global__ void k_pool(const float* __restrict__ h, const int* __restrict__ batch) {
    int base = blockIdx.x * 32;
    int col = threadIdx.x;
    int end = base + 32;
    if (end > N_NODES) end = N_NODES;
    if (base >= N_NODES) return;
    int cur = batch[base];
    float sum = 0.f;
    for (int n = base; n < end; n++) {
        int b = batch[n];
        if (b != cur) {
            atomicAdd(&g_pool[cur * HID + col], sum);
            sum = 0.f;
            cur = b;
        }
        sum += h[n * HID + col];
    }
    atomicAdd(&g_pool[cur * HID + col], sum);
}

// ---------------- output head ----------------
__global__ void k_out(const float* __restrict__ Wout, const float* __restrict__ bout,
                      float* __restrict__ out) {
    int t = threadIdx.x;
    if (t < NGRAPH * NCLASS) {
        int g = t / NCLASS;
        int c = t % NCLASS;
        float s = bout[c];
#pragma unroll 4
        for (int k = 0; k < HID; k++) s += g_pool[g * HID + k] * Wout[c * HID + k];
        out[t] = s;
    }
}

// ---------------- launch ----------------
extern "C" void kernel_launch(void* const* d_in, const int* in_sizes, int n_in,
                              void* d_out, int out_size) {
    const float* x = (const float*)d_in[0];
    const int* ei = (const int*)d_in[1];
    const int* src = ei;
    const int* dst = ei + N_EDGES;
    const int* batch = (const int*)d_in[2];
    const float* W1l = (const float*)d_in[3];
    const float* b1 = (const float*)d_in[4];
    const float* W1r = (const float*)d_in[5];
    const float* W2l = (const float*)d_in[6];
    const float* b2 = (const float*)d_in[7];
    const float* W2r = (const float*)d_in[8];
    const float* W3l = (const float*)d_in[9];
    const float* b3 = (const float*)d_in[10];
    const float* W3r = (const float*)d_in[11];
    const float* Wout = (const float*)d_in[12];
    const float* bout = (const float*)d_in[13];
    float* out = (float*)d_out;

    cudaFuncSetAttribute(k_proj, cudaFuncAttributeMaxDynamicSharedMemorySize, SMEM_P);

    uint4* d_Z; cudaGetSymbolAddress((void**)&d_Z, g_Z);
    uint4* d_Y; cudaGetSymbolAddress((void**)&d_Y, g_Y);
    float4* d_hA; cudaGetSymbolAddress((void**)&d_hA, g_hA);
    float4* d_hB; cudaGetSymbolAddress((void**)&d_hB, g_hB);
    uint4* d_Bh; cudaGetSymbolAddress((void**)&d_Bh, g_Bh);
    uint4* d_Bl; cudaGetSymbolAddress((void**)&d_Bl, g_Bl);

    // CSR build + weight precompute
    k_init<<<(N_NODES + 255) / 256, 256>>>();
    k_hist<<<(N_EDGES + 255) / 256, 256>>>(dst);
    k_wprep<<<128, 256>>>(W1l, W1r, (__nv_bfloat16*)(d_Bh), (__nv_bfloat16*)(d_Bl));
    k_wprep<<<128, 256>>>(W2l, W2r, (__nv_bfloat16*)(d_Bh + 4096),
                          (__nv_bfloat16*)(d_Bl + 4096));
    k_wprep<<<128, 256>>>(W3l, W3r, (__nv_bfloat16*)(d_Bh + 8192),
                          (__nv_bfloat16*)(d_Bl + 8192));
    k_scan1<<<SCAN_NB, 1024>>>();
    k_scan2<<<1, 1024>>>();
    k_scan3<<<(N_NODES + 255) / 256, 256>>>();
    k_scatter<<<(N_EDGES + 255) / 256, 256>>>(src, dst);

    // layer 1: x -> hA (relu)
    k_proj<<<PROJ_GRID, 256, SMEM_P>>>(x, d_Bh, d_Bl, b1, d_Z, d_Y);
    k_agg2<<<(N_NODES / 2 + 7) / 8, 256>>>(d_Z, d_Y, d_hA, 1);
    // layer 2: hA -> hB (relu)
    k_proj<<<PROJ_GRID, 256, SMEM_P>>>((const float*)d_hA, d_Bh + 4096, d_Bl + 4096,
                                       b2, d_Z, d_Y);
    k_agg2<<<(N_NODES / 2 + 7) / 8, 256>>>(d_Z, d_Y, d_hB, 1);
    // layer 3: hB -> hA (no relu)
    k_proj<<<PROJ_GRID, 256, SMEM_P>>>((const float*)d_hB, d_Bh + 8192, d_Bl + 8192,
                                       b3, d_Z, d_Y);
    k_agg2<<<(N_NODES / 2 + 7) / 8, 256>>>(d_Z, d_Y, d_hA, 0);

    // pooling + head
    k_pool<<<(N_NODES + 31) / 32, 128>>>((const float*)d_hA, batch);
    k_out<<<1, 640>>>(Wout, bout, out);
}